// round 2
// baseline (speedup 1.0000x reference)
#include <cuda_runtime.h>
#include <cuda_bf16.h>
#include <cstdint>

// Problem constants
#define NN   4096
#define DD   128
#define RR   8
#define OUTD 128
#define BB   4096

// Scratch (device globals: allocation-free)
__device__ float g_W[RR * NN * OUTD];   // 16 MB: W_r = emb @ K_r  (tf32-rounded)
__device__ float g_P[RR * NN * OUTD];   // 16 MB: P_r = adj_r @ W_r (fp32 partials)

// ---------------- helpers ----------------
__device__ __forceinline__ uint32_t f2tf32(float f) {
    uint32_t u;
    asm("cvt.rna.tf32.f32 %0, %1;" : "=r"(u) : "f"(f));
    return u;
}

__device__ __forceinline__ void cp16(void* smem_dst, const void* gmem_src) {
    uint32_t sa = (uint32_t)__cvta_generic_to_shared(smem_dst);
    asm volatile("cp.async.cg.shared.global [%0], [%1], 16;" :: "r"(sa), "l"(gmem_src));
}

__device__ __forceinline__ void mma_tf32(float d[4], const uint32_t a[4],
                                         const uint32_t b[2], const float c[4]) {
    asm volatile(
        "mma.sync.aligned.m16n8k8.row.col.f32.tf32.tf32.f32 "
        "{%0,%1,%2,%3}, {%4,%5,%6,%7}, {%8,%9}, {%10,%11,%12,%13};"
        : "=f"(d[0]), "=f"(d[1]), "=f"(d[2]), "=f"(d[3])
        : "r"(a[0]), "r"(a[1]), "r"(a[2]), "r"(a[3]),
          "r"(b[0]), "r"(b[1]),
          "f"(c[0]), "f"(c[1]), "f"(c[2]), "f"(c[3]));
}

// ---------------- kernel 1: W_r = emb @ K_r (fp32 FFMA, then RNA->tf32) --------
// grid (NN/32, RR), block 128.  Each block: 32 n-rows x 128 o-cols.
__global__ __launch_bounds__(128) void k1_relW(const float* __restrict__ emb,
                                               const float* __restrict__ relk) {
    __shared__ float es[32 * DD];  // 16 KB
    const int r  = blockIdx.y;
    const int n0 = blockIdx.x * 32;
    const int tid = threadIdx.x;   // = o

    // load emb tile (32x128)
    const float4* src = (const float4*)(emb + (size_t)n0 * DD);
    float4* dst = (float4*)es;
#pragma unroll
    for (int i = 0; i < 8; i++) dst[tid + i * 128] = src[tid + i * 128];
    __syncthreads();

    const float* K = relk + (size_t)r * DD * OUTD;
    float acc[32];
#pragma unroll
    for (int n = 0; n < 32; n++) acc[n] = 0.f;

    for (int d = 0; d < DD; d++) {
        float kv = K[d * OUTD + tid];
#pragma unroll
        for (int n = 0; n < 32; n++) acc[n] += es[n * DD + d] * kv;
    }

    float* Wr = g_W + ((size_t)r * NN + n0) * OUTD;
#pragma unroll
    for (int n = 0; n < 32; n++)
        Wr[n * OUTD + tid] = __uint_as_float(f2tf32(acc[n]));
}

// ---------------- kernel 2: P_r = adj_r @ W_r (tf32 mma, split over r) ---------
// grid (NN/128, RR), block 256 (8 warps). M-tile 128, N 128, K chunks of 16.
#define KB 16
#define A_STRIDE 20    // 16 + 4 pad -> conflict-free A-fragment LDS
#define B_STRIDE 136   // 128 + 8 pad -> conflict-free B-fragment LDS

__device__ __forceinline__ void load_tiles(const float* __restrict__ adjR,
                                           const float* __restrict__ Wr,
                                           int c, float* As, float* Bs, int tid) {
    const float* aSrc = adjR + c * KB;
#pragma unroll
    for (int i = 0; i < 2; i++) {
        int idx = tid + i * 256;        // 512 float4 = 128 rows x 4
        int row = idx >> 2, c4 = idx & 3;
        cp16(As + row * A_STRIDE + c4 * 4, aSrc + (size_t)row * NN + c4 * 4);
    }
    const float* bSrc = Wr + (size_t)c * KB * OUTD;
#pragma unroll
    for (int i = 0; i < 2; i++) {
        int idx = tid + i * 256;        // 512 float4 = 16 rows x 32
        int rk = idx >> 5, c4 = idx & 31;
        cp16(Bs + rk * B_STRIDE + c4 * 4, bSrc + rk * OUTD + c4 * 4);
    }
}

__global__ __launch_bounds__(256) void k2_gemm(const float* __restrict__ adj) {
    __shared__ float As[2][128 * A_STRIDE];   // 2 x 10 KB
    __shared__ float Bs[2][KB * B_STRIDE];    // 2 x 8.5 KB

    const int r  = blockIdx.y;
    const int mt = blockIdx.x;
    const float* adjR = adj + (size_t)r * NN * NN + (size_t)mt * 128 * NN;
    const float* Wr   = g_W + (size_t)r * NN * OUTD;

    const int tid  = threadIdx.x;
    const int warp = tid >> 5, lane = tid & 31;
    const int wm = warp & 3;       // 4 warps along M (32 rows each)
    const int wn = warp >> 2;      // 2 warps along N (64 cols each)
    const int g = lane >> 2, t = lane & 3;

    float acc[2][8][4];
#pragma unroll
    for (int i = 0; i < 2; i++)
#pragma unroll
        for (int j = 0; j < 8; j++)
#pragma unroll
            for (int v = 0; v < 4; v++) acc[i][j][v] = 0.f;

    const int NC = NN / KB;  // 256 chunks
    load_tiles(adjR, Wr, 0, As[0], Bs[0], tid);
    asm volatile("cp.async.commit_group;");

    for (int c = 0; c < NC; c++) {
        const int buf = c & 1;
        if (c + 1 < NC) {
            load_tiles(adjR, Wr, c + 1, As[buf ^ 1], Bs[buf ^ 1], tid);
            asm volatile("cp.async.commit_group;");
            asm volatile("cp.async.wait_group 1;");
        } else {
            asm volatile("cp.async.wait_group 0;");
        }
        __syncthreads();

#pragma unroll
        for (int ks = 0; ks < 2; ks++) {
            const int k0 = ks * 8;
            uint32_t a[2][4];
#pragma unroll
            for (int i = 0; i < 2; i++) {
                const int rowb = wm * 32 + i * 16;
                a[i][0] = f2tf32(As[buf][(rowb + g)     * A_STRIDE + k0 + t]);
                a[i][1] = f2tf32(As[buf][(rowb + g + 8) * A_STRIDE + k0 + t]);
                a[i][2] = f2tf32(As[buf][(rowb + g)     * A_STRIDE + k0 + t + 4]);
                a[i][3] = f2tf32(As[buf][(rowb + g + 8) * A_STRIDE + k0 + t + 4]);
            }
            uint32_t b[8][2];
#pragma unroll
            for (int j = 0; j < 8; j++) {
                const int cn = wn * 64 + j * 8 + g;
                b[j][0] = __float_as_uint(Bs[buf][(k0 + t)     * B_STRIDE + cn]);
                b[j][1] = __float_as_uint(Bs[buf][(k0 + t + 4) * B_STRIDE + cn]);
            }
#pragma unroll
            for (int i = 0; i < 2; i++)
#pragma unroll
                for (int j = 0; j < 8; j++)
                    mma_tf32(acc[i][j], a[i], b[j], acc[i][j]);
        }
        __syncthreads();
    }

    // epilogue -> g_P[r][mt*128 + row][col]
    float* Pr = g_P + (size_t)r * NN * OUTD + (size_t)mt * 128 * OUTD;
#pragma unroll
    for (int i = 0; i < 2; i++) {
        const int rowb = wm * 32 + i * 16 + g;
#pragma unroll
        for (int j = 0; j < 8; j++) {
            const int col = wn * 64 + j * 8 + t * 2;
            float2 v0 = make_float2(acc[i][j][0], acc[i][j][1]);
            float2 v1 = make_float2(acc[i][j][2], acc[i][j][3]);
            *(float2*)(Pr + (size_t)rowb * OUTD + col)       = v0;
            *(float2*)(Pr + (size_t)(rowb + 8) * OUTD + col) = v1;
        }
    }
}

// ---------------- kernel 3: out = e @ SK + sum_r P_r[idx] ---------------------
// grid (BB/64, 2 branches), block 256.
__global__ __launch_bounds__(256) void k3_out(const float* __restrict__ he,
                                              const int*   __restrict__ hi,
                                              const float* __restrict__ te,
                                              const int*   __restrict__ ti,
                                              const float* __restrict__ selfk,
                                              float* __restrict__ out) {
    __shared__ float es[64 * DD];   // 32 KB
    __shared__ int   idxs[64];

    const int branch = blockIdx.y;
    const float* e   = branch ? te : he;
    const int*   idx = branch ? ti : hi;
    const int b0 = blockIdx.x * 64;
    const int tid = threadIdx.x;

    const float4* src = (const float4*)(e + (size_t)b0 * DD);
    float4* dst = (float4*)es;
#pragma unroll
    for (int i = 0; i < 8; i++) dst[tid + i * 256] = src[tid + i * 256];
    if (tid < 64) idxs[tid] = idx[b0 + tid];
    __syncthreads();

    const int o  = tid & 127;
    const int bh = tid >> 7;     // 0 or 1 -> 32 b-rows each

    float acc[32];
#pragma unroll
    for (int bb = 0; bb < 32; bb++) acc[bb] = 0.f;

    for (int d = 0; d < DD; d++) {
        float sk = selfk[d * OUTD + o];
#pragma unroll
        for (int bb = 0; bb < 32; bb++)
            acc[bb] += es[(bh * 32 + bb) * DD + d] * sk;
    }

#pragma unroll
    for (int bb = 0; bb < 32; bb++) {
        const int bl = bh * 32 + bb;
        const int id = idxs[bl];
        const float* Pp = g_P + (size_t)id * OUTD + o;
        float s = 0.f;
#pragma unroll
        for (int rr = 0; rr < RR; rr++)
            s += Pp[(size_t)rr * NN * OUTD];
        out[(size_t)branch * BB * OUTD + (size_t)(b0 + bl) * OUTD + o] = acc[bb] + s;
    }
}

// ---------------- launch ------------------------------------------------------
extern "C" void kernel_launch(void* const* d_in, const int* in_sizes, int n_in,
                              void* d_out, int out_size) {
    const float* emb   = (const float*)d_in[0];
    const int*   hidx  = (const int*)  d_in[1];
    const float* he    = (const float*)d_in[2];
    const int*   tidx  = (const int*)  d_in[3];
    const float* te    = (const float*)d_in[4];
    const float* adj   = (const float*)d_in[5];
    const float* relk  = (const float*)d_in[6];
    const float* selfk = (const float*)d_in[7];
    float* out = (float*)d_out;

    k1_relW<<<dim3(NN / 32, RR), 128>>>(emb, relk);
    k2_gemm<<<dim3(NN / 128, RR), 256>>>(adj);
    k3_out<<<dim3(BB / 64, 2), 256>>>(he, hidx, te, tidx, selfk, out);
}

// round 8
// speedup vs baseline: 1.7050x; 1.7050x over previous
#include <cuda_runtime.h>
#include <cuda_fp16.h>
#include <cstdint>

// Problem constants
#define NN   4096
#define DD   128
#define RR   8
#define OUTD 128
#define BB   4096

// Scratch (device globals: allocation-free)
__device__ float g_Kt[(RR + 1) * DD * OUTD];        // [9][o][d] transposed kernels
__device__ float g_Wt[(size_t)RR * OUTD * NN];      // [8][o][n]  W transposed (fp32)
__device__ float g_P [(size_t)RR * NN * OUTD];      // [8][n][o]
__device__ float g_S [(size_t)2 * OUTD * BB];       // [2][o][b]  self-kernel term

// ---------------------------------------------------------------- helpers ----
// pack two fp32 -> f16x2 {lo, hi}   (cvt d,a,b => hi=a, lo=b)
__device__ __forceinline__ uint32_t pack_h2(float lo, float hi) {
    uint32_t r;
    asm("cvt.rn.f16x2.f32 %0, %1, %2;" : "=r"(r) : "f"(hi), "f"(lo));
    return r;
}

__device__ __forceinline__ void ldm_x4(uint32_t* r, uint32_t addr) {
    asm volatile("ldmatrix.sync.aligned.m8n8.x4.shared.b16 {%0,%1,%2,%3}, [%4];"
                 : "=r"(r[0]), "=r"(r[1]), "=r"(r[2]), "=r"(r[3]) : "r"(addr));
}

__device__ __forceinline__ void mma16816(float* d, const uint32_t* a, const uint32_t* b) {
    asm volatile("mma.sync.aligned.m16n8k16.row.col.f32.f16.f16.f32 "
                 "{%0,%1,%2,%3}, {%4,%5,%6,%7}, {%8,%9}, {%0,%1,%2,%3};"
                 : "+f"(d[0]), "+f"(d[1]), "+f"(d[2]), "+f"(d[3])
                 : "r"(a[0]), "r"(a[1]), "r"(a[2]), "r"(a[3]),
                   "r"(b[0]), "r"(b[1]));
}

// ----------------- k0: transpose relk (8) + selfk (1) -> g_Kt[z][o][d] -------
__global__ void k0_transpose(const float* __restrict__ relk,
                             const float* __restrict__ selfk) {
    __shared__ float t[32][33];
    const int z = blockIdx.z;
    const float* src = (z < RR) ? (relk + (size_t)z * DD * OUTD) : selfk;
    const int bo = blockIdx.x * 32;   // o-tile
    const int bd = blockIdx.y * 32;   // d-tile
    const int tx = threadIdx.x, ty = threadIdx.y;

#pragma unroll
    for (int i = ty; i < 32; i += 8)
        t[i][tx] = src[(size_t)(bd + i) * OUTD + bo + tx];   // t[d'][o']
    __syncthreads();
    float* dst = g_Kt + (size_t)z * DD * OUTD;
#pragma unroll
    for (int i = ty; i < 32; i += 8)
        dst[(size_t)(bo + i) * DD + bd + tx] = t[tx][i];     // Kt[o][d]
}

// ----------------- kH: generic 128x128-tile fp16 mma.sync GEMM ---------------
// C_tile[m][n] = sum_k A[m][k] * B[n][k]   (fp32 in gmem, fp16 compute, fp32 acc)
#define KB   32
#define ASTR 40                       // halves per smem row (80B, conflict-free)
#define TILE_HALFS (128 * ASTR)       // 5120 halves = 10240 B per tile

__global__ __launch_bounds__(256) void kH(
    const float* __restrict__ A0, size_t aY, size_t aX, int lda,
    const float* __restrict__ B0, size_t bY, size_t bX, int ldb,
    float* __restrict__ C0, size_t cY, size_t cX, int ldc, int NC) {
    __shared__ __align__(16) uint16_t sA[2][TILE_HALFS];
    __shared__ __align__(16) uint16_t sB[2][TILE_HALFS];

    const int tid  = threadIdx.x;
    const int warp = tid >> 5, lane = tid & 31;
    const int wm = warp & 3, wn = warp >> 2;      // 4 (M) x 2 (N) warps
    const int gq = lane >> 2, tq = lane & 3;      // mma group / thread-in-group

    const float* A = A0 + blockIdx.y * aY + blockIdx.x * aX;
    const float* B = B0 + blockIdx.y * bY + blockIdx.x * bX;
    float*       C = C0 + blockIdx.y * cY + blockIdx.x * cX;

    // load geometry: thread -> (row0 = tid>>3, 4 consecutive k at (tid&7)*4)
    const int row0 = tid >> 3, c8 = tid & 7;

    // ldmatrix per-lane base addresses
    const int q = lane >> 3, r8 = lane & 7;
    const uint32_t sAu = (uint32_t)__cvta_generic_to_shared(sA);
    const uint32_t sBu = (uint32_t)__cvta_generic_to_shared(sB);
    // A matrices: row = wm*32 + i*16 + (q&1)*8 + r8, koff = ks*16 + (q>>1)*8
    const uint32_t aAddr0 = sAu + (uint32_t)(((wm * 32 + (q & 1) * 8 + r8) * ASTR + (q >> 1) * 8) * 2);
    // B matrices: n = wn*64 + jp*16 + (q>>1)*8 + r8, koff = ks*16 + (q&1)*8
    const uint32_t bAddr0 = sBu + (uint32_t)(((wn * 64 + (q >> 1) * 8 + r8) * ASTR + (q & 1) * 8) * 2);

    float acc[2][8][4];
#pragma unroll
    for (int i = 0; i < 2; i++)
#pragma unroll
        for (int j = 0; j < 8; j++)
#pragma unroll
            for (int v = 0; v < 4; v++) acc[i][j][v] = 0.f;

    float4 aR[4], bR[4];

#define GLOAD(m)                                                              \
    do {                                                                      \
        const float* ap = A + (size_t)row0 * lda + (m) * KB + c8 * 4;         \
        const float* bp = B + (size_t)row0 * ldb + (m) * KB + c8 * 4;         \
        _Pragma("unroll")                                                     \
        for (int i = 0; i < 4; i++) {                                         \
            aR[i] = *(const float4*)(ap + (size_t)(i * 32) * lda);            \
            bR[i] = *(const float4*)(bp + (size_t)(i * 32) * ldb);            \
        }                                                                     \
    } while (0)

#define CSTORE(buf)                                                           \
    do {                                                                      \
        _Pragma("unroll")                                                     \
        for (int i = 0; i < 4; i++) {                                         \
            const int off = (row0 + i * 32) * ASTR + c8 * 4;                  \
            *(uint2*)&sA[buf][off] =                                          \
                make_uint2(pack_h2(aR[i].x, aR[i].y), pack_h2(aR[i].z, aR[i].w)); \
            *(uint2*)&sB[buf][off] =                                          \
                make_uint2(pack_h2(bR[i].x, bR[i].y), pack_h2(bR[i].z, bR[i].w)); \
        }                                                                     \
    } while (0)

    GLOAD(0);

    for (int m = 0; m < NC; m++) {
        const int buf = m & 1;
        CSTORE(buf);
        __syncthreads();
        if (m + 1 < NC) GLOAD(m + 1);

        const uint32_t aB = aAddr0 + buf * (TILE_HALFS * 2);
        const uint32_t bB = bAddr0 + buf * (TILE_HALFS * 2);
#pragma unroll
        for (int ks = 0; ks < 2; ks++) {
            uint32_t af[2][4];
#pragma unroll
            for (int i = 0; i < 2; i++)
                ldm_x4(af[i], aB + i * (16 * ASTR * 2) + ks * 32);
            uint32_t bf[4][4];
#pragma unroll
            for (int jp = 0; jp < 4; jp++)
                ldm_x4(bf[jp], bB + jp * (16 * ASTR * 2) + ks * 32);
#pragma unroll
            for (int i = 0; i < 2; i++)
#pragma unroll
                for (int j = 0; j < 8; j++)
                    mma16816(acc[i][j], af[i], &bf[j >> 1][(j & 1) * 2]);
        }
        __syncthreads();
    }

    // epilogue
#pragma unroll
    for (int i = 0; i < 2; i++) {
        const int row = wm * 32 + i * 16 + gq;
#pragma unroll
        for (int j = 0; j < 8; j++) {
            const int col = wn * 64 + j * 8 + tq * 2;
            *(float2*)(C + (size_t)row * ldc + col)       = make_float2(acc[i][j][0], acc[i][j][1]);
            *(float2*)(C + (size_t)(row + 8) * ldc + col) = make_float2(acc[i][j][2], acc[i][j][3]);
        }
    }
}

// ----------------- k3: out[br][b][o] = S[br][o][b] + sum_r P[r][idx[b]][o] ---
__global__ __launch_bounds__(256) void k3_gather(const int* __restrict__ hi,
                                                 const int* __restrict__ ti,
                                                 float* __restrict__ out) {
    __shared__ int idxs[64];
    const int br = blockIdx.y;
    const int* idx = br ? ti : hi;
    const int b0 = blockIdx.x * 64;
    const int tid = threadIdx.x;
    if (tid < 64) idxs[tid] = idx[b0 + tid];
    __syncthreads();

    const int o  = tid & 127;
    const int bh = tid >> 7;   // which 32-row half

    const float* Sp = g_S + (size_t)br * OUTD * BB + (size_t)o * BB + b0 + bh * 32;
    float sv[32];
#pragma unroll
    for (int qv = 0; qv < 8; qv++) {
        float4 v = *(const float4*)(Sp + qv * 4);
        sv[qv * 4 + 0] = v.x; sv[qv * 4 + 1] = v.y;
        sv[qv * 4 + 2] = v.z; sv[qv * 4 + 3] = v.w;
    }

#pragma unroll
    for (int bb = 0; bb < 32; bb++) {
        const int bl = bh * 32 + bb;
        const int id = idxs[bl];
        const float* Pp = g_P + (size_t)id * OUTD + o;
        float s = sv[bb];
#pragma unroll
        for (int r = 0; r < RR; r++)
            s += Pp[(size_t)r * NN * OUTD];
        out[((size_t)br * BB + b0 + bl) * OUTD + o] = s;
    }
}

// ---------------- launch ------------------------------------------------------
extern "C" void kernel_launch(void* const* d_in, const int* in_sizes, int n_in,
                              void* d_out, int out_size) {
    const float* emb   = (const float*)d_in[0];
    const int*   hidx  = (const int*)  d_in[1];
    const float* he    = (const float*)d_in[2];
    const int*   tidx  = (const int*)  d_in[3];
    const float* te    = (const float*)d_in[4];
    const float* adj   = (const float*)d_in[5];
    const float* relk  = (const float*)d_in[6];
    const float* selfk = (const float*)d_in[7];
    float* out = (float*)d_out;

    void *pKt, *pWt, *pP, *pS;
    cudaGetSymbolAddress(&pKt, g_Kt);
    cudaGetSymbolAddress(&pWt, g_Wt);
    cudaGetSymbolAddress(&pP,  g_P);
    cudaGetSymbolAddress(&pS,  g_S);
    const float* Kt = (const float*)pKt;
    float* Wt = (float*)pWt;
    float* P  = (float*)pP;
    float* S  = (float*)pS;

    // 0) transpose kernels -> Kt[z][o][d]
    k0_transpose<<<dim3(4, 4, RR + 1), dim3(32, 8)>>>(relk, selfk);

    // 1) Wt[r][o][n] = Kt_r @ emb^T     (M=o=128, N=n tiles, K=d=128 -> NC=4)
    kH<<<dim3(NN / 128, RR), 256>>>(
        Kt, (size_t)DD * OUTD, 0, DD,
        emb, 0, (size_t)128 * DD, DD,
        Wt, (size_t)OUTD * NN, 128, NN,
        4);

    // 2) P[r][m][o] = adj_r @ Wt_r^T    (M=m tiles, N=o=128, K=n=4096 -> NC=128)
    kH<<<dim3(NN / 128, RR), 256>>>(
        adj, (size_t)NN * NN, (size_t)128 * NN, NN,
        Wt, (size_t)OUTD * NN, 0, NN,
        P, (size_t)NN * OUTD, (size_t)128 * OUTD, OUTD,
        NN / KB);

    // 3) S[br][o][b] = SKt @ e^T        (M=o=128, N=b tiles, K=d=128 -> NC=4)
    kH<<<dim3(BB / 128, 1), 256>>>(
        Kt + (size_t)RR * DD * OUTD, 0, 0, DD,
        he, 0, (size_t)128 * DD, DD,
        S, 0, 128, BB,
        4);
    kH<<<dim3(BB / 128, 1), 256>>>(
        Kt + (size_t)RR * DD * OUTD, 0, 0, DD,
        te, 0, (size_t)128 * DD, DD,
        S + (size_t)OUTD * BB, 0, 128, BB,
        4);

    // 4) gather + add
    k3_gather<<<dim3(BB / 64, 2), 256>>>(hidx, tidx, out);
}

// round 13
// speedup vs baseline: 2.3424x; 1.3738x over previous
#include <cuda_runtime.h>
#include <cuda_fp16.h>
#include <cstdint>

// Problem constants
#define NN   4096
#define DD   128
#define RR   8
#define OUTD 128
#define BB   4096

// Scratch (device globals: allocation-free)
__device__ float  g_Kt[(RR + 1) * DD * OUTD];       // [9][o][d] transposed kernels
__device__ __half g_Wh[(size_t)RR * OUTD * NN];     // [8][o][n]  W transposed (fp16)
__device__ float  g_P [(size_t)RR * NN * OUTD];     // [8][n][o]
__device__ float  g_S [(size_t)2 * OUTD * BB];      // [2][o][b]  self-kernel term

// ---------------------------------------------------------------- helpers ----
__device__ __forceinline__ uint32_t pack_h2(float lo, float hi) {
    uint32_t r;
    asm("cvt.rn.f16x2.f32 %0, %1, %2;" : "=r"(r) : "f"(hi), "f"(lo));
    return r;
}

__device__ __forceinline__ void ldm_x4(uint32_t* r, uint32_t addr) {
    asm volatile("ldmatrix.sync.aligned.m8n8.x4.shared.b16 {%0,%1,%2,%3}, [%4];"
                 : "=r"(r[0]), "=r"(r[1]), "=r"(r[2]), "=r"(r[3]) : "r"(addr));
}

__device__ __forceinline__ void mma16816(float* d, const uint32_t* a, const uint32_t* b) {
    asm volatile("mma.sync.aligned.m16n8k16.row.col.f32.f16.f16.f32 "
                 "{%0,%1,%2,%3}, {%4,%5,%6,%7}, {%8,%9}, {%0,%1,%2,%3};"
                 : "+f"(d[0]), "+f"(d[1]), "+f"(d[2]), "+f"(d[3])
                 : "r"(a[0]), "r"(a[1]), "r"(a[2]), "r"(a[3]),
                   "r"(b[0]), "r"(b[1]));
}

__device__ __forceinline__ void cp16(uint32_t smem_dst, const void* gmem_src) {
    asm volatile("cp.async.cg.shared.global [%0], [%1], 16;" :: "r"(smem_dst), "l"(gmem_src));
}

// ----------------- k0: transpose relk (8) + selfk (1) -> g_Kt[z][o][d] -------
__global__ void k0_transpose(const float* __restrict__ relk,
                             const float* __restrict__ selfk) {
    __shared__ float t[32][33];
    const int z = blockIdx.z;
    const float* src = (z < RR) ? (relk + (size_t)z * DD * OUTD) : selfk;
    const int bo = blockIdx.x * 32;
    const int bd = blockIdx.y * 32;
    const int tx = threadIdx.x, ty = threadIdx.y;

#pragma unroll
    for (int i = ty; i < 32; i += 8)
        t[i][tx] = src[(size_t)(bd + i) * OUTD + bo + tx];
    __syncthreads();
    float* dst = g_Kt + (size_t)z * DD * OUTD;
#pragma unroll
    for (int i = ty; i < 32; i += 8)
        dst[(size_t)(bo + i) * DD + bd + tx] = t[tx][i];
}

// ----------------- kH: generic 128x128-tile fp16 mma.sync GEMM ---------------
// C_tile[m][n] = sum_k A[m][k] * B[n][k]; fp32 in, fp32 acc, fp32 or fp16 out.
#define KB   32
#define ASTR 40
#define TILE_HALFS (128 * ASTR)

__global__ __launch_bounds__(256) void kH(
    const float* __restrict__ A0, size_t aY, size_t aX, int lda,
    const float* __restrict__ B0, size_t bY, size_t bX, int ldb,
    void* __restrict__ C0, size_t cY, size_t cX, int ldc, int NC, int half_out) {
    __shared__ __align__(16) uint16_t sA[2][TILE_HALFS];
    __shared__ __align__(16) uint16_t sB[2][TILE_HALFS];

    const int tid  = threadIdx.x;
    const int warp = tid >> 5, lane = tid & 31;
    const int wm = warp & 3, wn = warp >> 2;
    const int gq = lane >> 2, tq = lane & 3;

    const float* A = A0 + blockIdx.y * aY + blockIdx.x * aX;
    const float* B = B0 + blockIdx.y * bY + blockIdx.x * bX;

    const int row0 = tid >> 3, c8 = tid & 7;
    const int q = lane >> 3, r8 = lane & 7;
    const uint32_t sAu = (uint32_t)__cvta_generic_to_shared(sA);
    const uint32_t sBu = (uint32_t)__cvta_generic_to_shared(sB);
    const uint32_t aAddr0 = sAu + (uint32_t)(((wm * 32 + (q & 1) * 8 + r8) * ASTR + (q >> 1) * 8) * 2);
    const uint32_t bAddr0 = sBu + (uint32_t)(((wn * 64 + (q >> 1) * 8 + r8) * ASTR + (q & 1) * 8) * 2);

    float acc[2][8][4];
#pragma unroll
    for (int i = 0; i < 2; i++)
#pragma unroll
        for (int j = 0; j < 8; j++)
#pragma unroll
            for (int v = 0; v < 4; v++) acc[i][j][v] = 0.f;

    float4 aR[4], bR[4];

#define GLOAD(m)                                                              \
    do {                                                                      \
        const float* ap = A + (size_t)row0 * lda + (m) * KB + c8 * 4;         \
        const float* bp = B + (size_t)row0 * ldb + (m) * KB + c8 * 4;         \
        _Pragma("unroll")                                                     \
        for (int i = 0; i < 4; i++) {                                         \
            aR[i] = *(const float4*)(ap + (size_t)(i * 32) * lda);            \
            bR[i] = *(const float4*)(bp + (size_t)(i * 32) * ldb);            \
        }                                                                     \
    } while (0)

#define CSTORE(buf)                                                           \
    do {                                                                      \
        _Pragma("unroll")                                                     \
        for (int i = 0; i < 4; i++) {                                         \
            const int off = (row0 + i * 32) * ASTR + c8 * 4;                  \
            *(uint2*)&sA[buf][off] =                                          \
                make_uint2(pack_h2(aR[i].x, aR[i].y), pack_h2(aR[i].z, aR[i].w)); \
            *(uint2*)&sB[buf][off] =                                          \
                make_uint2(pack_h2(bR[i].x, bR[i].y), pack_h2(bR[i].z, bR[i].w)); \
        }                                                                     \
    } while (0)

    GLOAD(0);

    for (int m = 0; m < NC; m++) {
        const int buf = m & 1;
        CSTORE(buf);
        __syncthreads();
        if (m + 1 < NC) GLOAD(m + 1);

        const uint32_t aB = aAddr0 + buf * (TILE_HALFS * 2);
        const uint32_t bB = bAddr0 + buf * (TILE_HALFS * 2);
#pragma unroll
        for (int ks = 0; ks < 2; ks++) {
            uint32_t af[2][4];
#pragma unroll
            for (int i = 0; i < 2; i++)
                ldm_x4(af[i], aB + i * (16 * ASTR * 2) + ks * 32);
            uint32_t bf[4][4];
#pragma unroll
            for (int jp = 0; jp < 4; jp++)
                ldm_x4(bf[jp], bB + jp * (16 * ASTR * 2) + ks * 32);
#pragma unroll
            for (int i = 0; i < 2; i++)
#pragma unroll
                for (int j = 0; j < 8; j++)
                    mma16816(acc[i][j], af[i], &bf[j >> 1][(j & 1) * 2]);
        }
        __syncthreads();
    }

    // epilogue
    if (half_out) {
        __half* C = (__half*)C0 + blockIdx.y * cY + blockIdx.x * cX;
#pragma unroll
        for (int i = 0; i < 2; i++) {
            const int row = wm * 32 + i * 16 + gq;
#pragma unroll
            for (int j = 0; j < 8; j++) {
                const int col = wn * 64 + j * 8 + tq * 2;
                *(uint32_t*)(C + (size_t)row * ldc + col)       = pack_h2(acc[i][j][0], acc[i][j][1]);
                *(uint32_t*)(C + (size_t)(row + 8) * ldc + col) = pack_h2(acc[i][j][2], acc[i][j][3]);
            }
        }
    } else {
        float* C = (float*)C0 + blockIdx.y * cY + blockIdx.x * cX;
#pragma unroll
        for (int i = 0; i < 2; i++) {
            const int row = wm * 32 + i * 16 + gq;
#pragma unroll
            for (int j = 0; j < 8; j++) {
                const int col = wn * 64 + j * 8 + tq * 2;
                *(float2*)(C + (size_t)row * ldc + col)       = make_float2(acc[i][j][0], acc[i][j][1]);
                *(float2*)(C + (size_t)(row + 8) * ldc + col) = make_float2(acc[i][j][2], acc[i][j][3]);
            }
        }
    }
}

// ----------------- kP: P[r][m][o] = adj_r @ Wh_r^T  (occupancy-2 specialized) -
// A = adj fp32 (reg convert), B = Wh fp16 (cp.async, FULL tile: 2 x 16B/thread).
#define NCP 128

__global__ __launch_bounds__(256, 2) void kP(const float* __restrict__ adj,
                                             const __half* __restrict__ Wh,
                                             float* __restrict__ P) {
    __shared__ __align__(16) uint16_t sA[2][TILE_HALFS];
    __shared__ __align__(16) uint16_t sB[2][TILE_HALFS];

    const int tid  = threadIdx.x;
    const int warp = tid >> 5, lane = tid & 31;
    const int wm = warp & 3, wn = warp >> 2;
    const int gq = lane >> 2, tq = lane & 3;

    const int mt = blockIdx.x, r = blockIdx.y;
    const float*  A = adj + (size_t)r * NN * NN + (size_t)mt * 128 * NN;
    const __half* B = Wh + (size_t)r * OUTD * NN;
    float*        C = P + (size_t)r * NN * OUTD + (size_t)mt * 128 * OUTD;

    const int row0 = tid >> 3, c8 = tid & 7;       // A geometry
    const int rowB = tid >> 1, bseg = tid & 1;     // B cp.async geometry (2 x 16B)

    const int q = lane >> 3, r8 = lane & 7;
    const uint32_t sAu = (uint32_t)__cvta_generic_to_shared(sA);
    const uint32_t sBu = (uint32_t)__cvta_generic_to_shared(sB);
    const uint32_t aAddr0 = sAu + (uint32_t)(((wm * 32 + (q & 1) * 8 + r8) * ASTR + (q >> 1) * 8) * 2);
    const uint32_t bAddr0 = sBu + (uint32_t)(((wn * 64 + (q >> 1) * 8 + r8) * ASTR + (q & 1) * 8) * 2);
    // thread covers halves [bseg*16, bseg*16+16) of row rowB (32 B = 2 cp16)
    const uint32_t bDst0  = sBu + (uint32_t)((rowB * ASTR + bseg * 16) * 2);
    const __half*  bSrc0  = B + (size_t)rowB * NN + bseg * 16;

    float acc[2][8][4];
#pragma unroll
    for (int i = 0; i < 2; i++)
#pragma unroll
        for (int j = 0; j < 8; j++)
#pragma unroll
            for (int v = 0; v < 4; v++) acc[i][j][v] = 0.f;

    float4 aR[4];

#define GLOADA(m)                                                             \
    do {                                                                      \
        const float* ap = A + (size_t)row0 * NN + (m) * KB + c8 * 4;          \
        _Pragma("unroll")                                                     \
        for (int i = 0; i < 4; i++)                                           \
            aR[i] = *(const float4*)(ap + (size_t)(i * 32) * NN);             \
    } while (0)

#define CSTA(buf)                                                             \
    do {                                                                      \
        _Pragma("unroll")                                                     \
        for (int i = 0; i < 4; i++) {                                         \
            const int off = (row0 + i * 32) * ASTR + c8 * 4;                  \
            *(uint2*)&sA[buf][off] =                                          \
                make_uint2(pack_h2(aR[i].x, aR[i].y), pack_h2(aR[i].z, aR[i].w)); \
        }                                                                     \
    } while (0)

#define CPB(m, buf)                                                           \
    do {                                                                      \
        cp16(bDst0 + (buf) * (TILE_HALFS * 2), bSrc0 + (m) * KB);             \
        cp16(bDst0 + 16 + (buf) * (TILE_HALFS * 2), bSrc0 + (m) * KB + 8);    \
        asm volatile("cp.async.commit_group;");                               \
    } while (0)

    GLOADA(0);
    CPB(0, 0);

    for (int m = 0; m < NCP; m++) {
        const int buf = m & 1;
        CSTA(buf);
        if (m + 1 < NCP) {
            GLOADA(m + 1);
            CPB(m + 1, buf ^ 1);
            asm volatile("cp.async.wait_group 1;");
        } else {
            asm volatile("cp.async.wait_group 0;");
        }
        __syncthreads();

        const uint32_t aB = aAddr0 + buf * (TILE_HALFS * 2);
        const uint32_t bB = bAddr0 + buf * (TILE_HALFS * 2);
#pragma unroll
        for (int ks = 0; ks < 2; ks++) {
            uint32_t af[2][4];
#pragma unroll
            for (int i = 0; i < 2; i++)
                ldm_x4(af[i], aB + i * (16 * ASTR * 2) + ks * 32);
            uint32_t bf[4][4];
#pragma unroll
            for (int jp = 0; jp < 4; jp++)
                ldm_x4(bf[jp], bB + jp * (16 * ASTR * 2) + ks * 32);
#pragma unroll
            for (int i = 0; i < 2; i++)
#pragma unroll
                for (int j = 0; j < 8; j++)
                    mma16816(acc[i][j], af[i], &bf[j >> 1][(j & 1) * 2]);
        }
        __syncthreads();
    }

#pragma unroll
    for (int i = 0; i < 2; i++) {
        const int row = wm * 32 + i * 16 + gq;
#pragma unroll
        for (int j = 0; j < 8; j++) {
            const int col = wn * 64 + j * 8 + tq * 2;
            *(float2*)(C + (size_t)row * OUTD + col)       = make_float2(acc[i][j][0], acc[i][j][1]);
            *(float2*)(C + (size_t)(row + 8) * OUTD + col) = make_float2(acc[i][j][2], acc[i][j][3]);
        }
    }
}

// ----------------- k3: out[br][b][o] = S[br][o][b] + sum_r P[r][idx[b]][o] ---
__global__ __launch_bounds__(256) void k3_gather(const int* __restrict__ hi,
                                                 const int* __restrict__ ti,
                                                 float* __restrict__ out) {
    __shared__ int idxs[64];
    const int br = blockIdx.y;
    const int* idx = br ? ti : hi;
    const int b0 = blockIdx.x * 64;
    const int tid = threadIdx.x;
    if (tid < 64) idxs[tid] = idx[b0 + tid];
    __syncthreads();

    const int o  = tid & 127;
    const int bh = tid >> 7;

    const float* Sp = g_S + (size_t)br * OUTD * BB + (size_t)o * BB + b0 + bh * 32;
    float sv[32];
#pragma unroll
    for (int qv = 0; qv < 8; qv++) {
        float4 v = *(const float4*)(Sp + qv * 4);
        sv[qv * 4 + 0] = v.x; sv[qv * 4 + 1] = v.y;
        sv[qv * 4 + 2] = v.z; sv[qv * 4 + 3] = v.w;
    }

#pragma unroll
    for (int bb = 0; bb < 32; bb++) {
        const int bl = bh * 32 + bb;
        const int id = idxs[bl];
        const float* Pp = g_P + (size_t)id * OUTD + o;
        float s = sv[bb];
#pragma unroll
        for (int rr2 = 0; rr2 < RR; rr2++)
            s += Pp[(size_t)rr2 * NN * OUTD];
        out[((size_t)br * BB + b0 + bl) * OUTD + o] = s;
    }
}

// ---------------- launch ------------------------------------------------------
extern "C" void kernel_launch(void* const* d_in, const int* in_sizes, int n_in,
                              void* d_out, int out_size) {
    const float* emb   = (const float*)d_in[0];
    const int*   hidx  = (const int*)  d_in[1];
    const float* he    = (const float*)d_in[2];
    const int*   tidx  = (const int*)  d_in[3];
    const float* te    = (const float*)d_in[4];
    const float* adj   = (const float*)d_in[5];
    const float* relk  = (const float*)d_in[6];
    const float* selfk = (const float*)d_in[7];
    float* out = (float*)d_out;

    void *pKt, *pWh, *pP, *pS;
    cudaGetSymbolAddress(&pKt, g_Kt);
    cudaGetSymbolAddress(&pWh, g_Wh);
    cudaGetSymbolAddress(&pP,  g_P);
    cudaGetSymbolAddress(&pS,  g_S);
    const float* Kt = (const float*)pKt;
    __half* Wh = (__half*)pWh;
    float* P  = (float*)pP;
    float* S  = (float*)pS;

    // 0) transpose kernels -> Kt[z][o][d]
    k0_transpose<<<dim3(4, 4, RR + 1), dim3(32, 8)>>>(relk, selfk);

    // 1) Wh[r][o][n] = Kt_r @ emb^T  (fp16 output)
    kH<<<dim3(NN / 128, RR), 256>>>(
        Kt, (size_t)DD * OUTD, 0, DD,
        emb, 0, (size_t)128 * DD, DD,
        Wh, (size_t)OUTD * NN, 128, NN,
        4, 1);

    // 2) P[r][m][o] = adj_r @ Wh_r^T  (occupancy-2 specialized)
    kP<<<dim3(NN / 128, RR), 256>>>(adj, Wh, P);

    // 3) S[br][o][b] = SKt @ e^T
    kH<<<dim3(BB / 128, 1), 256>>>(
        Kt + (size_t)RR * DD * OUTD, 0, 0, DD,
        he, 0, (size_t)128 * DD, DD,
        S, 0, 128, BB,
        4, 0);
    kH<<<dim3(BB / 128, 1), 256>>>(
        Kt + (size_t)RR * DD * OUTD, 0, 0, DD,
        te, 0, (size_t)128 * DD, DD,
        S + (size_t)OUTD * BB, 0, 128, BB,
        4, 0);

    // 4) gather + add
    k3_gather<<<dim3(BB / 64, 2), 256>>>(hidx, tidx, out);
}